// round 15
// baseline (speedup 1.0000x reference)
#include <cuda_runtime.h>
#include <cstdint>

// Problem constants
#define B_NUM  4
#define T_SEQ  2048
#define C_DIM  2048
#define H_NUM  16
#define D_HEAD 128

// ---------------------------------------------------------------------------
// Scratch (no cudaMalloc allowed). All values tf32-pre-rounded.
// K-INTERLEAVE: every GEMM input (x, W_attn, W_proj, att) stores its
// contraction-dim columns permuted within 8-groups: u -> 2(u&3) + (u>>2)
// applied at write (pre-pass / attention epilogue). Both GEMM operands carry
// the identical permutation, so products pair correctly; fragment pairs
// (k=c, k=c+4) become adjacent -> LDS.64 in the GEMM hot loop.
// Q/K thirds of g_qkv additionally carry the d-column interleave (R14) for
// LDS.64 in attention. V third natural.
// ---------------------------------------------------------------------------
__device__ float g_qkv[(size_t)B_NUM * T_SEQ * 3 * C_DIM];
__device__ float g_att[(size_t)B_NUM * T_SEQ * C_DIM];
__device__ float g_x  [(size_t)B_NUM * T_SEQ * C_DIM];        // x, tf32, K-il
__device__ float g_wa [(size_t)3 * C_DIM * C_DIM];            // W_attn, tf32, K-il
__device__ float g_wp [(size_t)C_DIM * C_DIM];                // W_proj, tf32, K-il

// ---------------------------------------------------------------------------
// tf32 / math helpers
// ---------------------------------------------------------------------------
__device__ __forceinline__ uint32_t f2tf32(float x) {
    uint32_t r;
    asm("cvt.rna.tf32.f32 %0, %1;" : "=r"(r) : "f"(x));
    return r;
}
__device__ __forceinline__ float fexp2(float x) {
    float y;
    asm("ex2.approx.ftz.f32 %0, %1;" : "=f"(y) : "f"(x));
    return y;
}

// D += A(16x8) * B(8x8), tf32 in, f32 accumulate
__device__ __forceinline__ void mma_tf32(float d[4], const uint32_t a[4], const uint32_t b[2]) {
    asm("mma.sync.aligned.m16n8k8.row.col.f32.tf32.tf32.f32 "
        "{%0,%1,%2,%3}, {%4,%5,%6,%7}, {%8,%9}, {%0,%1,%2,%3};\n"
        : "+f"(d[0]), "+f"(d[1]), "+f"(d[2]), "+f"(d[3])
        : "r"(a[0]), "r"(a[1]), "r"(a[2]), "r"(a[3]), "r"(b[0]), "r"(b[1]));
}

__device__ __forceinline__ void cpasync16(uint32_t smaddr, const void* gptr) {
    asm volatile("cp.async.cg.shared.global [%0], [%1], 16;\n" :: "r"(smaddr), "l"(gptr));
}
__device__ __forceinline__ void cpasync_commit() {
    asm volatile("cp.async.commit_group;\n" ::: "memory");
}
template <int N>
__device__ __forceinline__ void cpasync_wait() {
    asm volatile("cp.async.wait_group %0;\n" :: "n"(N) : "memory");
}

__device__ __forceinline__ int il8(int u) {   // 8-group interleave
    return ((u & 3) << 1) | (u >> 2);
}

// ---------------------------------------------------------------------------
// tf32 round + K-interleave pre-pass. Processes one 8-col group per step:
// out[{0..7}] = {in0,in4,in1,in5,in2,in6,in3,in7}  (tf32-rounded)
// ---------------------------------------------------------------------------
__global__ void round_il_tf32_kernel(const float* __restrict__ in,
                                     float* __restrict__ outp, int n8)
{
    for (int i = blockIdx.x * blockDim.x + threadIdx.x; i < n8;
         i += gridDim.x * blockDim.x) {
        float4 a = reinterpret_cast<const float4*>(in)[2 * i];
        float4 b = reinterpret_cast<const float4*>(in)[2 * i + 1];
        float4 o0, o1;
        o0.x = __uint_as_float(f2tf32(a.x));   // in0
        o0.y = __uint_as_float(f2tf32(b.x));   // in4
        o0.z = __uint_as_float(f2tf32(a.y));   // in1
        o0.w = __uint_as_float(f2tf32(b.y));   // in5
        o1.x = __uint_as_float(f2tf32(a.z));   // in2
        o1.y = __uint_as_float(f2tf32(b.z));   // in6
        o1.z = __uint_as_float(f2tf32(a.w));   // in3
        o1.w = __uint_as_float(f2tf32(b.w));   // in7
        reinterpret_cast<float4*>(outp)[2 * i]     = o0;
        reinterpret_cast<float4*>(outp)[2 * i + 1] = o1;
    }
}

// ---------------------------------------------------------------------------
// NT GEMM, 3-stage cp.async ring: C[M,N] = A[M,K] * B[N,K]^T
// Inputs K-interleaved -> fragment pairs adjacent -> LDS.64 (96->48 LDS/ktile).
// RTF: epilogue rounds outputs to tf32; QKV's Q/K regions (cc<4096) also get
// the d-column interleave for attention.
// ---------------------------------------------------------------------------
#define G_BM 128
#define G_BN 128
#define G_BK 32
#define G_STR 36
#define G_TILE (G_BM * G_STR)
#define G_STAGES 3
#define G_SMEM (G_STAGES * 2 * G_TILE * 4)   // 108 KB

template <bool RTF>
__global__ __launch_bounds__(256, 2) void gemm_nt_tf32_db(
    const float* __restrict__ A, const float* __restrict__ B,
    float* __restrict__ C, int M, int N, int K)
{
    extern __shared__ uint32_t sm[];

    const int bm = blockIdx.y * G_BM;
    const int bn = blockIdx.x * G_BN;
    const int tid  = threadIdx.x;
    const int warp = tid >> 5;
    const int lane = tid & 31;
    const int g    = lane >> 2;
    const int tig  = lane & 3;
    const int wm = (warp >> 2) * 64;
    const int wn = (warp & 3) * 32;

    const int lr = tid >> 3;
    const int lc = (tid & 7) * 4;

    const float* Abase = A + (size_t)bm * K;
    const float* Bbase = B + (size_t)bn * K;

    float acc[4][4][4];
#pragma unroll
    for (int i = 0; i < 4; i++)
#pragma unroll
        for (int j = 0; j < 4; j++) {
            acc[i][j][0] = 0.f; acc[i][j][1] = 0.f;
            acc[i][j][2] = 0.f; acc[i][j][3] = 0.f;
        }

    const int ntiles = K / G_BK;

#pragma unroll
    for (int s = 0; s < 2; s++) {
        uint32_t sa = (uint32_t)__cvta_generic_to_shared(sm + s * 2 * G_TILE);
        uint32_t sb = sa + G_TILE * 4;
        const int k0 = s * G_BK;
#pragma unroll
        for (int rr = 0; rr < 4; rr++) {
            int row = lr + rr * 32;
            cpasync16(sa + (row * G_STR + lc) * 4, Abase + (size_t)row * K + k0 + lc);
            cpasync16(sb + (row * G_STR + lc) * 4, Bbase + (size_t)row * K + k0 + lc);
        }
        cpasync_commit();
    }

    int cur = 0;
    int nxt = 2;
    for (int i = 0; i < ntiles; i++) {
        if (i + 1 < ntiles) cpasync_wait<1>();
        else                cpasync_wait<0>();
        __syncthreads();

        const uint32_t* As = sm + cur * 2 * G_TILE;
        const uint32_t* Bs = As + G_TILE;

#pragma unroll
        for (int ks = 0; ks < 4; ks++) {
            const int c2 = ks * 8 + 2 * tig;   // interleaved pair (k=c, k=c+4)
            uint32_t af[4][4];
            uint32_t bf[4][2];
#pragma unroll
            for (int mf = 0; mf < 4; mf++) {
                int r = wm + mf * 16 + g;
                uint2 a0 = *reinterpret_cast<const uint2*>(&As[r * G_STR + c2]);
                uint2 a1 = *reinterpret_cast<const uint2*>(&As[(r + 8) * G_STR + c2]);
                af[mf][0] = a0.x; af[mf][1] = a1.x;
                af[mf][2] = a0.y; af[mf][3] = a1.y;
            }
#pragma unroll
            for (int nf = 0; nf < 4; nf++) {
                int n = wn + nf * 8 + g;
                uint2 b0 = *reinterpret_cast<const uint2*>(&Bs[n * G_STR + c2]);
                bf[nf][0] = b0.x; bf[nf][1] = b0.y;
            }
#pragma unroll
            for (int mf = 0; mf < 4; mf++)
#pragma unroll
                for (int nf = 0; nf < 4; nf++)
                    mma_tf32(acc[mf][nf], af[mf], bf[nf]);
        }

        if (i + 2 < ntiles) {
            const int k0 = (i + 2) * G_BK;
            uint32_t sa = (uint32_t)__cvta_generic_to_shared(sm + nxt * 2 * G_TILE);
            uint32_t sb = sa + G_TILE * 4;
#pragma unroll
            for (int rr = 0; rr < 4; rr++) {
                int row = lr + rr * 32;
                cpasync16(sa + (row * G_STR + lc) * 4, Abase + (size_t)row * K + k0 + lc);
                cpasync16(sb + (row * G_STR + lc) * 4, Bbase + (size_t)row * K + k0 + lc);
            }
            cpasync_commit();
        }

        cur = (cur == G_STAGES - 1) ? 0 : cur + 1;
        nxt = (nxt == G_STAGES - 1) ? 0 : nxt + 1;
    }

    // QKV output: Q/K regions (cc < 4096) get the d-column interleave.
    const bool ileave = RTF && (bn < 4096);
#pragma unroll
    for (int mf = 0; mf < 4; mf++) {
        int r = bm + wm + mf * 16 + g;
#pragma unroll
        for (int nf = 0; nf < 4; nf++) {
            int cc = bn + wn + nf * 8 + 2 * tig;
            float v0 = acc[mf][nf][0], v1 = acc[mf][nf][1];
            float v2 = acc[mf][nf][2], v3 = acc[mf][nf][3];
            if (RTF) {
                v0 = __uint_as_float(f2tf32(v0));
                v1 = __uint_as_float(f2tf32(v1));
                v2 = __uint_as_float(f2tf32(v2));
                v3 = __uint_as_float(f2tf32(v3));
            }
            if (ileave) {
                int base = cc & ~7, u = cc & 7;
                int c0 = base + il8(u), c1 = base + il8(u + 1);
                C[(size_t)r * N + c0]       = v0;
                C[(size_t)r * N + c1]       = v1;
                C[(size_t)(r + 8) * N + c0] = v2;
                C[(size_t)(r + 8) * N + c1] = v3;
            } else {
                *reinterpret_cast<float2*>(&C[(size_t)r * N + cc])       = make_float2(v0, v1);
                *reinterpret_cast<float2*>(&C[(size_t)(r + 8) * N + cc]) = make_float2(v2, v3);
            }
        }
    }
}

// ---------------------------------------------------------------------------
// Flash attention (causal), tf32 MMA, base-2 online softmax.
// (R14 structure: single barrier+wait/iter, K triple / V double buffered,
//  Q/K d-interleaved -> LDS.64 fragment pairs.)
// Epilogue writes att tf32-rounded AND K-interleaved (proj GEMM contraction).
// ---------------------------------------------------------------------------
#define Q_TILE 128
#define KV_STR 132
#define V_STR  136
#define P_STR  68
#define KV_TILE (64 * KV_STR)
#define V_TILE  (64 * V_STR)
#define ATT_SMEM ((3 * KV_TILE + 2 * V_TILE + Q_TILE * P_STR) * 4)

__device__ __forceinline__ void cp_tile64(uint32_t saddr, const float* __restrict__ src,
                                          int tid, int sstr)
{
#pragma unroll
    for (int i = 0; i < 8; i++) {
        int idx = tid + i * 256;
        int r = idx >> 5;
        int c4 = (idx & 31) << 2;
        cpasync16(saddr + (r * sstr + c4) * 4, src + (size_t)r * (3 * C_DIM) + c4);
    }
}

__global__ __launch_bounds__(256, 1) void attn_kernel(const float* __restrict__ qkv,
                                                      float* __restrict__ out)
{
    extern __shared__ uint32_t sm[];
    uint32_t* sV0 = sm + 3 * KV_TILE;
    uint32_t* sV1 = sm + 3 * KV_TILE + V_TILE;
    uint32_t* sP  = sm + 3 * KV_TILE + 2 * V_TILE;
    uint32_t* sK2 = sm + 2 * KV_TILE;

    const uint32_t smb  = (uint32_t)__cvta_generic_to_shared(sm);
    const uint32_t sV0a = smb + (3 * KV_TILE) * 4;
    const uint32_t sV1a = sV0a + V_TILE * 4;
    const uint32_t sPa  = sV1a + V_TILE * 4;
    const uint32_t sK2a = smb + (2 * KV_TILE) * 4;

    const int qt = gridDim.x - 1 - blockIdx.x;   // LPT
    const int b  = blockIdx.y >> 4;
    const int h  = blockIdx.y & 15;
    const int tid  = threadIdx.x;
    const int warp = tid >> 5;
    const int lane = tid & 31;
    const int g   = lane >> 2;
    const int tig = lane & 3;
    const int wq  = warp * 16;
    const float scale = 0.12751744f;   // (1/sqrt(128)) * log2(e)

    const float* qbase = qkv + (size_t)b * T_SEQ * 3 * C_DIM + h * D_HEAD;
    const float* kbase = qbase + C_DIM;
    const float* vbase = qbase + 2 * C_DIM;

    cp_tile64(sK2a, qbase + (size_t)(qt * Q_TILE) * (3 * C_DIM), tid, KV_STR);
    cp_tile64(sPa,  qbase + (size_t)(qt * Q_TILE + 64) * (3 * C_DIM), tid, KV_STR);
    cpasync_commit();
    cpasync_wait<0>();
    __syncthreads();

    cp_tile64(smb + 0 * KV_TILE * 4, kbase + 0, tid, KV_STR);
    cpasync_commit();
    cp_tile64(sV0a, vbase + 0, tid, V_STR);
    cpasync_commit();
    cp_tile64(smb + 1 * KV_TILE * 4, kbase + (size_t)64 * (3 * C_DIM), tid, KV_STR);
    cpasync_commit();

    const uint32_t* qsrc = (warp < 4) ? sK2 : sP;
    const int qrow = (wq & 63);
    uint32_t qf[16][4];
#pragma unroll
    for (int ks = 0; ks < 16; ks++) {
        int c2 = ks * 8 + 2 * tig;
        uint2 u0 = *reinterpret_cast<const uint2*>(&qsrc[(qrow + g) * KV_STR + c2]);
        uint2 u1 = *reinterpret_cast<const uint2*>(&qsrc[(qrow + g + 8) * KV_STR + c2]);
        qf[ks][0] = u0.x;
        qf[ks][1] = u1.x;
        qf[ks][2] = u0.y;
        qf[ks][3] = u1.y;
    }

    float of[16][4];
#pragma unroll
    for (int i = 0; i < 16; i++) { of[i][0] = 0.f; of[i][1] = 0.f; of[i][2] = 0.f; of[i][3] = 0.f; }
    float m0 = -1e30f, m1 = -1e30f, l0 = 0.f, l1 = 0.f;

    const int gr0 = qt * Q_TILE + wq + g;
    const int jmax = 2 * qt + 1;

    for (int j = 0; j <= jmax; j++) {
        const uint32_t* sKc = sm + (j % 3) * KV_TILE;
        const uint32_t* sVc = (j & 1) ? sV1 : sV0;

        const bool live = (j * 64 <= qt * Q_TILE + wq + 15);

        if (j < jmax) cpasync_wait<1>();
        else          cpasync_wait<0>();
        __syncthreads();

        if (j + 1 <= jmax) {
            cp_tile64((j & 1) ? sV0a : sV1a,
                      vbase + (size_t)((j + 1) * 64) * (3 * C_DIM), tid, V_STR);
            cpasync_commit();
        }
        if (j + 2 <= jmax) {
            cp_tile64(smb + ((j + 2) % 3) * KV_TILE * 4,
                      kbase + (size_t)((j + 2) * 64) * (3 * C_DIM), tid, KV_STR);
            cpasync_commit();
        }

        float sacc[8][4];
#pragma unroll
        for (int nf = 0; nf < 8; nf++) { sacc[nf][0]=0.f; sacc[nf][1]=0.f; sacc[nf][2]=0.f; sacc[nf][3]=0.f; }
        if (live) {
#pragma unroll
            for (int ks = 0; ks < 16; ks++) {
                int c2 = ks * 8 + 2 * tig;
#pragma unroll
                for (int nf = 0; nf < 8; nf++) {
                    uint2 kv = *reinterpret_cast<const uint2*>(&sKc[(nf * 8 + g) * KV_STR + c2]);
                    uint32_t bfr[2] = { kv.x, kv.y };
                    mma_tf32(sacc[nf], qf[ks], bfr);
                }
            }

#pragma unroll
            for (int nf = 0; nf < 8; nf++) {
                sacc[nf][0] *= scale; sacc[nf][1] *= scale;
                sacc[nf][2] *= scale; sacc[nf][3] *= scale;
            }
            if ((j + 1) * 64 - 1 > qt * Q_TILE + wq) {
                int r1 = gr0 + 8;
#pragma unroll
                for (int nf = 0; nf < 8; nf++) {
                    int gcb = j * 64 + nf * 8 + 2 * tig;
                    if (gcb     > gr0) sacc[nf][0] = -1e30f;
                    if (gcb + 1 > gr0) sacc[nf][1] = -1e30f;
                    if (gcb     > r1)  sacc[nf][2] = -1e30f;
                    if (gcb + 1 > r1)  sacc[nf][3] = -1e30f;
                }
            }

            float mx0 = -1e30f, mx1 = -1e30f;
#pragma unroll
            for (int nf = 0; nf < 8; nf++) {
                mx0 = fmaxf(mx0, fmaxf(sacc[nf][0], sacc[nf][1]));
                mx1 = fmaxf(mx1, fmaxf(sacc[nf][2], sacc[nf][3]));
            }
            mx0 = fmaxf(mx0, __shfl_xor_sync(0xffffffffu, mx0, 1));
            mx0 = fmaxf(mx0, __shfl_xor_sync(0xffffffffu, mx0, 2));
            mx1 = fmaxf(mx1, __shfl_xor_sync(0xffffffffu, mx1, 1));
            mx1 = fmaxf(mx1, __shfl_xor_sync(0xffffffffu, mx1, 2));
            float mn0 = fmaxf(m0, mx0), mn1 = fmaxf(m1, mx1);
            float a0 = fexp2(m0 - mn0), a1 = fexp2(m1 - mn1);
            m0 = mn0; m1 = mn1;

            float rs0 = 0.f, rs1 = 0.f;
#pragma unroll
            for (int nf = 0; nf < 8; nf++) {
                float p0 = fexp2(sacc[nf][0] - mn0);
                float p1 = fexp2(sacc[nf][1] - mn0);
                float p2 = fexp2(sacc[nf][2] - mn1);
                float p3 = fexp2(sacc[nf][3] - mn1);
                rs0 += p0 + p1; rs1 += p2 + p3;
                int cb = nf * 8 + 2 * tig;
                *reinterpret_cast<uint2*>(&sP[(wq + g) * P_STR + cb]) =
                    make_uint2(f2tf32(p0), f2tf32(p1));
                *reinterpret_cast<uint2*>(&sP[(wq + g + 8) * P_STR + cb]) =
                    make_uint2(f2tf32(p2), f2tf32(p3));
            }
            rs0 += __shfl_xor_sync(0xffffffffu, rs0, 1);
            rs0 += __shfl_xor_sync(0xffffffffu, rs0, 2);
            rs1 += __shfl_xor_sync(0xffffffffu, rs1, 1);
            rs1 += __shfl_xor_sync(0xffffffffu, rs1, 2);
            l0 = l0 * a0 + rs0;
            l1 = l1 * a1 + rs1;
#pragma unroll
            for (int nf = 0; nf < 16; nf++) {
                of[nf][0] *= a0; of[nf][1] *= a0;
                of[nf][2] *= a1; of[nf][3] *= a1;
            }
            __syncwarp();

#pragma unroll
            for (int ks = 0; ks < 8; ks++) {
                int c = ks * 8 + tig;
                uint32_t pf[4];
                pf[0] = sP[(wq + g) * P_STR + c];
                pf[1] = sP[(wq + g + 8) * P_STR + c];
                pf[2] = sP[(wq + g) * P_STR + c + 4];
                pf[3] = sP[(wq + g + 8) * P_STR + c + 4];
#pragma unroll
                for (int nf = 0; nf < 16; nf++) {
                    uint32_t bfr[2];
                    bfr[0] = sVc[(ks * 8 + tig) * V_STR + nf * 8 + g];
                    bfr[1] = sVc[(ks * 8 + tig + 4) * V_STR + nf * 8 + g];
                    mma_tf32(of[nf], pf, bfr);
                }
            }
        }
    }

    // epilogue: normalize, tf32-round, write att with K-interleave (the proj
    // GEMM contracts over these columns).
    float i0 = 1.f / l0, i1 = 1.f / l1;
    int r0 = gr0;
    int r1 = gr0 + 8;
    float* o0 = out + ((size_t)b * T_SEQ + r0) * C_DIM + h * D_HEAD;
    float* o1 = out + ((size_t)b * T_SEQ + r1) * C_DIM + h * D_HEAD;
    const int u0 = il8(2 * tig), u1 = il8(2 * tig + 1);
#pragma unroll
    for (int nf = 0; nf < 16; nf++) {
        int base = nf * 8;
        o0[base + u0] = __uint_as_float(f2tf32(of[nf][0] * i0));
        o0[base + u1] = __uint_as_float(f2tf32(of[nf][1] * i0));
        o1[base + u0] = __uint_as_float(f2tf32(of[nf][2] * i1));
        o1[base + u1] = __uint_as_float(f2tf32(of[nf][3] * i1));
    }
}

// ---------------------------------------------------------------------------
// kernel_launch
// ---------------------------------------------------------------------------
extern "C" void kernel_launch(void* const* d_in, const int* in_sizes, int n_in,
                              void* d_out, int out_size)
{
    (void)in_sizes; (void)n_in; (void)out_size;
    const float* x  = (const float*)d_in[0];
    const float* Wa = (const float*)d_in[1];
    const float* Wp = (const float*)d_in[2];
    float* out = (float*)d_out;

    float *qkv, *att, *xr, *war, *wpr;
    cudaGetSymbolAddress((void**)&qkv, g_qkv);
    cudaGetSymbolAddress((void**)&att, g_att);
    cudaGetSymbolAddress((void**)&xr,  g_x);
    cudaGetSymbolAddress((void**)&war, g_wa);
    cudaGetSymbolAddress((void**)&wpr, g_wp);

    cudaFuncSetAttribute(gemm_nt_tf32_db<true>,  cudaFuncAttributeMaxDynamicSharedMemorySize, G_SMEM);
    cudaFuncSetAttribute(gemm_nt_tf32_db<false>, cudaFuncAttributeMaxDynamicSharedMemorySize, G_SMEM);
    cudaFuncSetAttribute(attn_kernel, cudaFuncAttributeMaxDynamicSharedMemorySize, ATT_SMEM);

    const int M = B_NUM * T_SEQ;   // 8192

    // 0) tf32-round + K-interleave inputs once
    round_il_tf32_kernel<<<2048, 256>>>(x,  xr,  (B_NUM * T_SEQ * C_DIM) / 8);
    round_il_tf32_kernel<<<2048, 256>>>(Wa, war, (3 * C_DIM * C_DIM) / 8);
    round_il_tf32_kernel<<<1024, 256>>>(Wp, wpr, (C_DIM * C_DIM) / 8);

    // 1) qkv = x @ W_attn^T  (tf32-rounded, Q/K d-interleaved)
    dim3 g1(3 * C_DIM / G_BN, M / G_BM);
    gemm_nt_tf32_db<true><<<g1, 256, G_SMEM>>>(xr, war, qkv, M, 3 * C_DIM, C_DIM);

    // 2) causal flash attention -> att (tf32-rounded, K-interleaved)
    dim3 g2(T_SEQ / Q_TILE, B_NUM * H_NUM);
    attn_kernel<<<g2, 256, ATT_SMEM>>>(qkv, att);

    // 3) out = att @ W_proj^T  (full fp32 outputs, natural column order)
    dim3 g3(C_DIM / G_BN, M / G_BM);
    gemm_nt_tf32_db<false><<<g3, 256, G_SMEM>>>(att, wpr, out, M, C_DIM, C_DIM);
}